// round 8
// baseline (speedup 1.0000x reference)
#include <cuda_runtime.h>
#include <cuda_bf16.h>
#include <cstdint>

#define DV      256
#define KEMB    1024
#define MTILE   128
#define NTILE   128
#define NCHUNK  8

/* dynamic smem layout (bytes) */
#define OFF_A       0            /* 128 x 512B bf16 X tile (swizzled)   */
#define OFF_B       65536        /* 128 x 512B bf16 E chunk (swizzled)  */
#define OFF_S       131072       /* 128 x 512B fp32 scores (swizzled)   */
#define OFF_CAND_S  196608       /* 256 x 8 floats top-8 scores         */
#define OFF_CAND_I  204800       /* 256 x 8 ints   top-8 indices        */
#define OFF_BIAS    212992       /* 1024 floats: 0.5*||e||^2            */
#define OFF_IDX     217088       /* 128 ints winning index per row      */
#define OFF_RED     217600       /* 8 doubles loss partials             */
#define SMEM_TOTAL  217664

__device__ __align__(16) __nv_bfloat16 g_emb_bf16[KEMB * DV];
__device__ float  g_bias[KEMB];     /* 0.5*||e||^2 (screen only)            */
__device__ float  g_bsq[KEMB];      /* ||e||^2, reference-order fp32 sum    */
__device__ double g_loss_acc;

static __device__ __forceinline__ uint32_t smem_u32(const void* p) {
    uint32_t a;
    asm("{ .reg .u64 t; cvta.to.shared.u64 t, %1; cvt.u32.u64 %0, t; }" : "=r"(a) : "l"(p));
    return a;
}

/* XOR swizzle on 16B chunks within a 512B row: conflict-free ldmatrix */
static __device__ __forceinline__ uint32_t swz(int row, int chunk) {
    return (uint32_t)(row * 512) + (uint32_t)((chunk ^ (row & 7)) << 4);
}

static __device__ __forceinline__ void ldsm4(uint32_t* r, uint32_t addr) {
    asm volatile("ldmatrix.sync.aligned.m8n8.x4.shared.b16 {%0,%1,%2,%3}, [%4];"
                 : "=r"(r[0]), "=r"(r[1]), "=r"(r[2]), "=r"(r[3]) : "r"(addr));
}

static __device__ __forceinline__ void mma16816(float* c, const uint32_t* a,
                                                uint32_t b0, uint32_t b1) {
    asm volatile(
        "mma.sync.aligned.m16n8k16.row.col.f32.bf16.bf16.f32 "
        "{%0,%1,%2,%3}, {%4,%5,%6,%7}, {%8,%9}, {%0,%1,%2,%3};"
        : "+f"(c[0]), "+f"(c[1]), "+f"(c[2]), "+f"(c[3])
        : "r"(a[0]), "r"(a[1]), "r"(a[2]), "r"(a[3]), "r"(b0), "r"(b1));
}

/* ---------------- Kernel A: codebook prep ----------------
   B_i = ||e_i||^2 computed EXACTLY like the reference's jnp.sum(emb*emb,1):
   strictly sequential fp32 adds of unfused fp32 products, natural order. */
__global__ void vq_prep(const float* __restrict__ emb) {
    int b = blockIdx.x, t = threadIdx.x;           /* 1024 blocks x 256 threads */
    float v = emb[(size_t)b * DV + t];
    g_emb_bf16[(size_t)b * DV + t] = __float2bfloat16(v);
    if (t == 0) {
        const float4* er = (const float4*)(emb + (size_t)b * DV);
        float s = 0.f;
#pragma unroll 8
        for (int i = 0; i < DV / 4; i++) {
            float4 e = er[i];
            s = __fadd_rn(s, __fmul_rn(e.x, e.x));
            s = __fadd_rn(s, __fmul_rn(e.y, e.y));
            s = __fadd_rn(s, __fmul_rn(e.z, e.z));
            s = __fadd_rn(s, __fmul_rn(e.w, e.w));
        }
        g_bsq[b]  = s;
        g_bias[b] = 0.5f * s;
        if (b == 0) g_loss_acc = 0.0;
    }
}

/* ---------------- Kernel B: main ---------------- */
__global__ void __launch_bounds__(256, 1)
vq_main(const float* __restrict__ x, const float* __restrict__ emb, float* __restrict__ outq) {
    extern __shared__ char smem[];
    const uint32_t sb = smem_u32(smem);
    const int t = threadIdx.x;
    const int w = t >> 5;
    const int l = t & 31;
    const int m0 = blockIdx.x * MTILE;

    /* ---- load X tile -> bf16 swizzled smem A; biases -> smem ---- */
    {
        int row = t >> 1, half = t & 1;
        const float4* xr = (const float4*)(x + (size_t)(m0 + row) * DV + half * 128);
#pragma unroll
        for (int c = 0; c < 16; c++) {
            float4 v0 = xr[2 * c], v1 = xr[2 * c + 1];
            __nv_bfloat162 p0 = __floats2bfloat162_rn(v0.x, v0.y);
            __nv_bfloat162 p1 = __floats2bfloat162_rn(v0.z, v0.w);
            __nv_bfloat162 p2 = __floats2bfloat162_rn(v1.x, v1.y);
            __nv_bfloat162 p3 = __floats2bfloat162_rn(v1.z, v1.w);
            uint4 st;
            st.x = *reinterpret_cast<uint32_t*>(&p0);
            st.y = *reinterpret_cast<uint32_t*>(&p1);
            st.z = *reinterpret_cast<uint32_t*>(&p2);
            st.w = *reinterpret_cast<uint32_t*>(&p3);
            *reinterpret_cast<uint4*>(smem + OFF_A + swz(row, half * 16 + c)) = st;
        }
#pragma unroll
        for (int i = 0; i < 4; i++)
            ((float*)(smem + OFF_BIAS))[i * 256 + t] = g_bias[i * 256 + t];
    }

    /* warp tile: rows wr..wr+31, cols wc..wc+63 of the 128x128 chunk scores */
    const int wr = (w >> 1) * 32, wc = (w & 1) * 64;

    /* per-lane ldmatrix row bases (fixed across chunks/ksteps) */
    uint32_t aBase[2], aXor[2], bBase[4], bXor[4];
    const uint32_t aoff = (uint32_t)(l >> 4);          /* A: k-chunk +1 for lanes>=16 */
    const uint32_t boff = (uint32_t)((l >> 3) & 1);    /* B: k-chunk +1 for lanes 8-15,24-31 */
#pragma unroll
    for (int i = 0; i < 2; i++) {
        int r = wr + i * 16 + (l & 7) + ((l >> 3) & 1) * 8;
        aBase[i] = sb + OFF_A + (uint32_t)(r * 512);
        aXor[i] = (uint32_t)(r & 7);
    }
#pragma unroll
    for (int nt = 0; nt < 4; nt++) {
        int r = wc + nt * 16 + (l & 7) + ((l >= 16) ? 8 : 0);
        bBase[nt] = sb + OFF_B + (uint32_t)(r * 512);
        bXor[nt] = (uint32_t)(r & 7);
    }

    /* score epilogue / scan bases */
    const int erow = wr + (l >> 2);
    const int ecol = wc + (l & 3) * 2;
    const int srow = t & 127, shalf = t >> 7;          /* scan: thread -> (row, half) */
    float* sbias = (float*)(smem + OFF_BIAS);

    float ts[8]; int ti[8];
#pragma unroll
    for (int p = 0; p < 8; p++) { ts[p] = -3.0e38f; ti[p] = 0x7fffffff; }

    for (int c = 0; c < NCHUNK; c++) {
        /* ---- load E chunk c ---- */
        {
            int row = t >> 1, half = t & 1;
            const uint4* er = (const uint4*)(g_emb_bf16 + (size_t)(c * NTILE + row) * DV + half * 128);
#pragma unroll
            for (int k = 0; k < 16; k++)
                *reinterpret_cast<uint4*>(smem + OFF_B + swz(row, half * 16 + k)) = er[k];
        }
        __syncthreads();   /* B ready; previous scan done -> S reusable */

        /* ---- GEMM: scores = X * E^T (bf16 -> fp32) ---- */
        float acc[2][8][4];
#pragma unroll
        for (int i = 0; i < 2; i++)
#pragma unroll
            for (int j = 0; j < 8; j++)
#pragma unroll
                for (int q = 0; q < 4; q++) acc[i][j][q] = 0.f;

#pragma unroll
        for (int k = 0; k < 16; k++) {
            uint32_t a[2][4], b[4][4];
#pragma unroll
            for (int i = 0; i < 2; i++)
                ldsm4(a[i], aBase[i] + ((((uint32_t)(2 * k) + aoff) ^ aXor[i]) << 4));
#pragma unroll
            for (int nt = 0; nt < 4; nt++)
                ldsm4(b[nt], bBase[nt] + ((((uint32_t)(2 * k) + boff) ^ bXor[nt]) << 4));
#pragma unroll
            for (int i = 0; i < 2; i++)
#pragma unroll
                for (int j = 0; j < 8; j++)
                    mma16816(acc[i][j], a[i], b[j >> 1][(j & 1) * 2], b[j >> 1][(j & 1) * 2 + 1]);
        }

        /* ---- store scores to swizzled smem ---- */
#pragma unroll
        for (int i = 0; i < 2; i++) {
            int r0 = erow + i * 16;
#pragma unroll
            for (int j = 0; j < 8; j++) {
                int col = ecol + j * 8;
                uint32_t coff = (uint32_t)((((col >> 2) ^ (r0 & 7)) << 4) + (col & 3) * 4);
                uint32_t coff8 = (uint32_t)(((((col >> 2) ^ ((r0 + 8) & 7)) << 4)) + (col & 3) * 4);
                *reinterpret_cast<float2*>(smem + OFF_S + (uint32_t)(r0 * 512) + coff) =
                    make_float2(acc[i][j][0], acc[i][j][1]);
                *reinterpret_cast<float2*>(smem + OFF_S + (uint32_t)((r0 + 8) * 512) + coff8) =
                    make_float2(acc[i][j][2], acc[i][j][3]);
            }
        }
        __syncthreads();

        /* ---- scan: thread owns (row srow, half shalf): 64 cols, keep top-8 of
                s = x.e - 0.5||e||^2  (maximize == minimize distance) ---- */
        const float* bias_c = sbias + c * NTILE;
#pragma unroll
        for (int cc = 0; cc < 16; cc++) {
            int chunk = shalf * 16 + cc;
            float4 v = *reinterpret_cast<const float4*>(smem + OFF_S + swz(srow, chunk));
            float4 bv = *reinterpret_cast<const float4*>(bias_c + chunk * 4);
            float sc[4] = { v.x - bv.x, v.y - bv.y, v.z - bv.z, v.w - bv.w };
#pragma unroll
            for (int j = 0; j < 4; j++) {
                float s = sc[j];
                if (s > ts[7]) {
                    float cs = s; int ci = c * NTILE + chunk * 4 + j;
#pragma unroll
                    for (int p = 0; p < 8; p++) {
                        if (cs > ts[p]) {
                            float tv = ts[p]; int tx = ti[p];
                            ts[p] = cs; ti[p] = ci; cs = tv; ci = tx;
                        }
                    }
                }
            }
        }
        __syncthreads();   /* scan done before next chunk overwrites B and S */
    }

    /* ---- publish per-thread top-8 candidate lists ---- */
    {
        float* cs = (float*)(smem + OFF_CAND_S) + t * 8;
        int*   ci = (int*)(smem + OFF_CAND_I) + t * 8;
#pragma unroll
        for (int p = 0; p < 8; p++) { cs[p] = ts[p]; ci[p] = ti[p]; }
    }
    __syncthreads();

    /* ---- refinement: replicate the reference's fp32 arithmetic ORDER.
            Reference: A = seq fp32 sum of unfused x*x (XLA CPU reduce, no
            reassoc, no fma);  M = seq fused-FMA chain over k (Eigen GEBP /
            cublas per-thread accumulation);  d = fl(fl(A+B) - 2*M);
            argmin with ties -> lowest index. Threads 0..127: one row each. ---- */
    double bestd64 = 0.0;
    if (t < 128) {
        const float* cs0 = (const float*)(smem + OFF_CAND_S) + t * 8;
        const float* cs1 = (const float*)(smem + OFF_CAND_S) + (t + 128) * 8;
        const int*   ci0 = (const int*)(smem + OFF_CAND_I) + t * 8;
        const int*   ci1 = (const int*)(smem + OFF_CAND_I) + (t + 128) * 8;
        float sstar = fmaxf(cs0[0], cs1[0]);
        float thr = sstar - 0.05f;                  /* ~15-sigma bf16-noise margin */
        const float4* xr = (const float4*)(x + (size_t)(m0 + t) * DV);

        /* A = ||x||^2: strictly sequential, unfused mul+add, natural order */
        float Af = 0.f;
#pragma unroll 8
        for (int i = 0; i < DV / 4; i++) {
            float4 v = xr[i];
            Af = __fadd_rn(Af, __fmul_rn(v.x, v.x));
            Af = __fadd_rn(Af, __fmul_rn(v.y, v.y));
            Af = __fadd_rn(Af, __fmul_rn(v.z, v.z));
            Af = __fadd_rn(Af, __fmul_rn(v.w, v.w));
        }

        float bestq = 3.4e38f; int besti = 0x7fffffff;
        for (int src = 0; src < 2; src++) {
            const float* cs = src ? cs1 : cs0;
            const int*   ci = src ? ci1 : ci0;
#pragma unroll 1
            for (int p = 0; p < 8; p++) {
                if (cs[p] < thr) break;
                int idx = ci[p];
                const float4* er = (const float4*)(emb + (size_t)idx * DV);
                /* M = x.e: strictly sequential fused-FMA chain, natural order */
                float Mf = 0.f;
#pragma unroll 8
                for (int i = 0; i < DV / 4; i++) {
                    float4 xv = xr[i]; float4 ev = er[i];
                    Mf = __fmaf_rn(xv.x, ev.x, Mf);
                    Mf = __fmaf_rn(xv.y, ev.y, Mf);
                    Mf = __fmaf_rn(xv.z, ev.z, Mf);
                    Mf = __fmaf_rn(xv.w, ev.w, Mf);
                }
                float Bf = g_bsq[idx];
                float dq = __fsub_rn(__fadd_rn(Af, Bf), __fmul_rn(2.0f, Mf));
                if (dq < bestq || (dq == bestq && idx < besti)) {
                    bestq = dq; besti = idx;
                }
            }
        }
        ((int*)(smem + OFF_IDX))[t] = besti;
        bestd64 = (double)bestq;        /* ~1e-6-relative accurate loss term */
    }

    /* ---- loss reduction (sum of chosen-row distances) ---- */
    {
        double v = (t < 128) ? bestd64 : 0.0;
#pragma unroll
        for (int o = 16; o; o >>= 1) {
            v += __longlong_as_double(__shfl_down_sync(0xffffffffu, __double_as_longlong(v), o));
        }
        if (l == 0) ((double*)(smem + OFF_RED))[w] = v;
    }
    __syncthreads();
    if (t == 0) {
        double s = 0.0;
#pragma unroll
        for (int i = 0; i < 8; i++) s += ((double*)(smem + OFF_RED))[i];
        atomicAdd(&g_loss_acc, s);
    }

    /* ---- coalesced gather write: out[row] = emb[idx[row]] ---- */
    const int* sidx = (const int*)(smem + OFF_IDX);
    const float4* e4 = (const float4*)emb;
    float4* o4 = (float4*)outq;
#pragma unroll 4
    for (int i = t; i < MTILE * (DV / 4); i += 256) {
        int r = i >> 6, cc = i & 63;
        o4[(size_t)(m0 + r) * (DV / 4) + cc] = e4[(size_t)sidx[r] * (DV / 4) + cc];
    }
}

/* ---------------- Kernel C: finalize loss ---------------- */
__global__ void vq_finalize(float* loss_out, double inv_n) {
    if (threadIdx.x == 0) *loss_out = (float)(2.0 * g_loss_acc * inv_n);
}

extern "C" void kernel_launch(void* const* d_in, const int* in_sizes, int n_in,
                              void* d_out, int out_size) {
    const float* x   = (const float*)d_in[0];
    const float* emb = (const float*)d_in[1];
    float* out = (float*)d_out;
    const int nx = in_sizes[0];          /* 64*32*32*256 = 16777216 */
    const int rows = nx / DV;            /* 65536 */

    cudaFuncSetAttribute(vq_main, cudaFuncAttributeMaxDynamicSharedMemorySize, SMEM_TOTAL);

    vq_prep<<<KEMB, 256>>>(emb);
    vq_main<<<rows / MTILE, 256, SMEM_TOTAL>>>(x, emb, out);
    vq_finalize<<<1, 32>>>(out + (out_size - 1), 1.0 / (double)nx);
}

// round 10
// speedup vs baseline: 1.3303x; 1.3303x over previous
#include <cuda_runtime.h>
#include <cuda_bf16.h>
#include <cstdint>

#define DV      256
#define KEMB    1024
#define MTILE   128
#define NTILE   128
#define NCHUNK  8
#define KSTEP   8            /* 256 / 32 per s8 IMMA */

/* dynamic smem layout (bytes) */
#define OFF_A       0        /* 128 x 256B int8 X tile (swizzled)        */
#define OFF_B       32768    /* 128 x 256B int8 E chunk (swizzled)       */
#define OFF_SC      65536    /* 1024 x float2 {se, 16-0.5||e||^2} = 8KB  */
#define OFF_SX      73728    /* 128 floats: per-row x scale              */
#define OFF_CAND    74240    /* 128 rows x 32 packed cands = 16KB        */
#define OFF_IDX     90624    /* 128 ints winning index per row           */
#define OFF_RED     91136    /* 8 doubles loss partials                  */
#define SMEM_TOTAL  91200

__device__ __align__(16) uint32_t g_emb_i8[KEMB * (DV / 4)];
__device__ __align__(16) float2 g_sb[KEMB];   /* {se, 16 - 0.5*||e||^2} */
__device__ float  g_bsq[KEMB];                /* ||e||^2 ref-order fp32 */
__device__ double g_loss_acc;

static __device__ __forceinline__ uint32_t smem_u32(const void* p) {
    uint32_t a;
    asm("{ .reg .u64 t; cvta.to.shared.u64 t, %1; cvt.u32.u64 %0, t; }" : "=r"(a) : "l"(p));
    return a;
}

/* XOR swizzle on 16B chunks within a 256B int8 row */
static __device__ __forceinline__ uint32_t swz(int row, int chunk) {
    return (uint32_t)(row * 256) + (uint32_t)((chunk ^ (row & 7)) << 4);
}

static __device__ __forceinline__ void ldsm4(uint32_t* r, uint32_t addr) {
    asm volatile("ldmatrix.sync.aligned.m8n8.x4.shared.b16 {%0,%1,%2,%3}, [%4];"
                 : "=r"(r[0]), "=r"(r[1]), "=r"(r[2]), "=r"(r[3]) : "r"(addr));
}

/* s8 IMMA: D[16,8] += A[16,32] * B[32,8], s32 accum */
static __device__ __forceinline__ void imma16832(int* c, const uint32_t* a,
                                                 uint32_t b0, uint32_t b1) {
    asm volatile(
        "mma.sync.aligned.m16n8k32.row.col.s32.s8.s8.s32 "
        "{%0,%1,%2,%3}, {%4,%5,%6,%7}, {%8,%9}, {%0,%1,%2,%3};"
        : "+r"(c[0]), "+r"(c[1]), "+r"(c[2]), "+r"(c[3])
        : "r"(a[0]), "r"(a[1]), "r"(a[2]), "r"(a[3]), "r"(b0), "r"(b1));
}

/* sorted top-4 insert on packed {score|idx} uints */
static __device__ __forceinline__ void ins4(uint32_t* L, uint32_t pb) {
    if (pb > L[3]) {
        if (pb > L[1]) {
            if (pb > L[0]) { L[3] = L[2]; L[2] = L[1]; L[1] = L[0]; L[0] = pb; }
            else           { L[3] = L[2]; L[2] = L[1]; L[1] = pb; }
        } else {
            if (pb > L[2]) { L[3] = L[2]; L[2] = pb; }
            else           { L[3] = pb; }
        }
    }
}

static __device__ __forceinline__ uint32_t pack4(float4 v, float inv) {
    int a = __float2int_rn(v.x * inv) & 255;
    int b = __float2int_rn(v.y * inv) & 255;
    int c = __float2int_rn(v.z * inv) & 255;
    int d = __float2int_rn(v.w * inv) & 255;
    return (uint32_t)a | ((uint32_t)b << 8) | ((uint32_t)c << 16) | ((uint32_t)d << 24);
}

/* ---------------- Kernel A: codebook prep ----------------
   per-row int8 quantization + scale; ||e||^2 in the reference's exact
   order (strictly sequential fp32 adds of unfused products). */
__global__ void vq_prep(const float* __restrict__ emb) {
    int b = blockIdx.x, t = threadIdx.x;           /* 1024 blocks x 256 threads */
    float v = emb[(size_t)b * DV + t];
    float av = fabsf(v);
#pragma unroll
    for (int o = 16; o; o >>= 1) av = fmaxf(av, __shfl_xor_sync(0xffffffffu, av, o));
    __shared__ float sw[8];
    __shared__ float smax;
    if ((t & 31) == 0) sw[t >> 5] = av;
    __syncthreads();
    if (t == 0) {
        float m = sw[0];
#pragma unroll
        for (int i = 1; i < 8; i++) m = fmaxf(m, sw[i]);
        smax = m;
    }
    __syncthreads();
    float m = smax;
    float inv = 127.0f / m;
    uint32_t qb = (uint32_t)(__float2int_rn(v * inv) & 255);
    uint32_t p1 = __shfl_down_sync(0xffffffffu, qb, 1);
    uint32_t p2 = __shfl_down_sync(0xffffffffu, qb, 2);
    uint32_t p3 = __shfl_down_sync(0xffffffffu, qb, 3);
    if ((t & 3) == 0)
        g_emb_i8[b * 64 + (t >> 2)] = qb | (p1 << 8) | (p2 << 16) | (p3 << 24);
    if (t == 0) {
        const float4* er = (const float4*)(emb + (size_t)b * DV);
        float s = 0.f;
#pragma unroll 8
        for (int i = 0; i < DV / 4; i++) {
            float4 e = er[i];
            s = __fadd_rn(s, __fmul_rn(e.x, e.x));
            s = __fadd_rn(s, __fmul_rn(e.y, e.y));
            s = __fadd_rn(s, __fmul_rn(e.z, e.z));
            s = __fadd_rn(s, __fmul_rn(e.w, e.w));
        }
        g_bsq[b] = s;
        g_sb[b] = make_float2(m * (1.0f / 127.0f), 16.0f - 0.5f * s);
        if (b == 0) g_loss_acc = 0.0;
    }
}

/* ---------------- Kernel B: main ---------------- */
__global__ void __launch_bounds__(256, 2)
vq_main(const float* __restrict__ x, const float* __restrict__ emb, float* __restrict__ outq) {
    extern __shared__ char smem[];
    const uint32_t sb = smem_u32(smem);
    const int t = threadIdx.x;
    const int w = t >> 5;
    const int l = t & 31;
    const int m0 = blockIdx.x * MTILE;

    /* ---- stage per-code {se, 16-bias} table ---- */
    {
        const float4* src = (const float4*)g_sb;
        float4* dst = (float4*)(smem + OFF_SC);
        dst[t] = src[t];
        dst[t + 256] = src[t + 256];
    }

    /* ---- X: per-row absmax then int8 quantize into swizzled smem ---- */
    {
        int row = t >> 1, half = t & 1;
        const float4* xr = (const float4*)(x + (size_t)(m0 + row) * DV + half * 128);
        float mx = 0.f;
#pragma unroll 8
        for (int i = 0; i < 32; i++) {
            float4 v = xr[i];
            mx = fmaxf(mx, fmaxf(fmaxf(fabsf(v.x), fabsf(v.y)), fmaxf(fabsf(v.z), fabsf(v.w))));
        }
        mx = fmaxf(mx, __shfl_xor_sync(0xffffffffu, mx, 1));
        float inv = 127.0f / mx;
        if (half == 0) ((float*)(smem + OFF_SX))[row] = mx * (1.0f / 127.0f);
#pragma unroll
        for (int c = 0; c < 8; c++) {
            uint4 st;
            st.x = pack4(xr[4 * c + 0], inv);
            st.y = pack4(xr[4 * c + 1], inv);
            st.z = pack4(xr[4 * c + 2], inv);
            st.w = pack4(xr[4 * c + 3], inv);
            *reinterpret_cast<uint4*>(smem + OFF_A + swz(row, half * 8 + c)) = st;
        }
    }
    __syncthreads();

    /* warp tile: rows wr..wr+31, cols wc..wc+63 of the 128x128 chunk scores */
    const int wr = (w >> 1) * 32, wc = (w & 1) * 64;
    const uint32_t aoff = (uint32_t)(l >> 4);
    const uint32_t boff = (uint32_t)((l >> 3) & 1);
    uint32_t aAddr[2], aX[2], bAddr[4], bX[4];
#pragma unroll
    for (int i = 0; i < 2; i++) {
        int r = wr + i * 16 + (l & 7) + ((l >> 3) & 1) * 8;
        aAddr[i] = sb + OFF_A + (uint32_t)(r * 256);
        aX[i] = (uint32_t)(r & 7);
    }
#pragma unroll
    for (int nt = 0; nt < 4; nt++) {
        int r = wc + nt * 16 + (l & 7) + ((l >= 16) ? 8 : 0);
        bAddr[nt] = sb + OFF_B + (uint32_t)(r * 256);
        bX[nt] = (uint32_t)(r & 7);
    }
    const int erow = wr + (l >> 2);
    const int ecol = wc + (l & 3) * 2;

    /* per-thread rows: erow + (ri>>1)*16 + (ri&1)*8 */
    float sx[4];
#pragma unroll
    for (int ri = 0; ri < 4; ri++)
        sx[ri] = ((const float*)(smem + OFF_SX))[erow + (ri >> 1) * 16 + (ri & 1) * 8];

    uint32_t L[4][4];
#pragma unroll
    for (int ri = 0; ri < 4; ri++)
#pragma unroll
        for (int p = 0; p < 4; p++) L[ri][p] = 0u;

    const float4* scp = (const float4*)(smem + OFF_SC);

    for (int c = 0; c < NCHUNK; c++) {
        if (c) __syncthreads();    /* prior chunk's MMA reads of B done */
        /* ---- load E chunk c (int8) ---- */
        {
            int row = t >> 1, half = t & 1;
            const uint4* er = (const uint4*)(g_emb_i8 + (size_t)(c * NTILE + row) * 64) + half * 8;
#pragma unroll
            for (int k = 0; k < 8; k++)
                *reinterpret_cast<uint4*>(smem + OFF_B + swz(row, half * 8 + k)) = er[k];
        }
        __syncthreads();

        /* ---- GEMM: int8 dot products, s32 accum ---- */
        int acc[2][8][4];
#pragma unroll
        for (int i = 0; i < 2; i++)
#pragma unroll
            for (int j = 0; j < 8; j++)
#pragma unroll
                for (int q = 0; q < 4; q++) acc[i][j][q] = 0;

#pragma unroll
        for (int s = 0; s < KSTEP; s++) {
            uint32_t a[2][4], bfr[4][4];
#pragma unroll
            for (int i = 0; i < 2; i++)
                ldsm4(a[i], aAddr[i] + ((((uint32_t)(2 * s) + aoff) ^ aX[i]) << 4));
#pragma unroll
            for (int nt = 0; nt < 4; nt++)
                ldsm4(bfr[nt], bAddr[nt] + ((((uint32_t)(2 * s) + boff) ^ bX[nt]) << 4));
#pragma unroll
            for (int i = 0; i < 2; i++)
#pragma unroll
                for (int j = 0; j < 8; j++)
                    imma16832(acc[i][j], a[i], bfr[j >> 1][(j & 1) * 2], bfr[j >> 1][(j & 1) * 2 + 1]);
        }

        /* ---- register-resident scan: s = sx*se*dot + (16 - 0.5||e||^2);
                pack {score, 10-bit code idx} and keep per-row top-4 ---- */
#pragma unroll
        for (int j = 0; j < 8; j++) {
            int colg = c * NTILE + ecol + j * 8;
            float4 sc2 = scp[colg >> 1];   /* {se0, c16_0, se1, c16_1} */
#pragma unroll
            for (int ri = 0; ri < 4; ri++) {
                int i = ri >> 1, qb = (ri & 1) * 2;
                float F0 = __int2float_rn(acc[i][j][qb]);
                float F1 = __int2float_rn(acc[i][j][qb + 1]);
                float s0 = __fmaf_rn(sx[ri], sc2.x * F0, sc2.y);
                float s1 = __fmaf_rn(sx[ri], sc2.z * F1, sc2.w);
                ins4(L[ri], (__float_as_uint(s0) & 0xFFFFFC00u) | (uint32_t)colg);
                ins4(L[ri], (__float_as_uint(s1) & 0xFFFFFC00u) | (uint32_t)(colg + 1));
            }
        }
    }
    __syncthreads();

    /* ---- publish candidate lists: row r gets 32 packed entries ---- */
    {
        uint32_t* cand = (uint32_t*)(smem + OFF_CAND);
#pragma unroll
        for (int ri = 0; ri < 4; ri++) {
            int r = erow + (ri >> 1) * 16 + (ri & 1) * 8;
            *reinterpret_cast<uint4*>(cand + r * 32 + (w & 1) * 16 + (l & 3) * 4) =
                make_uint4(L[ri][0], L[ri][1], L[ri][2], L[ri][3]);
        }
    }
    __syncthreads();

    /* ---- refinement: replicate the reference's fp32 arithmetic ORDER
            (validated R8): A = seq unfused sum of x*x; M = seq FMA chain;
            d = fl(fl(A+B) - 2*M); argmin ties -> lowest index. ---- */
    double bestd64 = 0.0;
    if (t < 128) {
        const uint32_t* cl = (const uint32_t*)(smem + OFF_CAND) + t * 32;
        uint32_t cb[32];
#pragma unroll
        for (int k = 0; k < 8; k++)
            *reinterpret_cast<uint4*>(cb + k * 4) = reinterpret_cast<const uint4*>(cl)[k];
        uint32_t bestpb = 0;
#pragma unroll
        for (int k = 0; k < 32; k++) bestpb = max(bestpb, cb[k]);
        float thrv = __uint_as_float(bestpb & 0xFFFFFC00u) - 0.08f;

        const float4* xr = (const float4*)(x + (size_t)(m0 + t) * DV);
        float Af = 0.f;
#pragma unroll 8
        for (int i = 0; i < DV / 4; i++) {
            float4 v = xr[i];
            Af = __fadd_rn(Af, __fmul_rn(v.x, v.x));
            Af = __fadd_rn(Af, __fmul_rn(v.y, v.y));
            Af = __fadd_rn(Af, __fmul_rn(v.z, v.z));
            Af = __fadd_rn(Af, __fmul_rn(v.w, v.w));
        }

        float bestq = 3.4e38f; int besti = 0x7fffffff;
#pragma unroll 1
        for (int k = 0; k < 32; k++) {
            uint32_t pb = cb[k];
            if (__uint_as_float(pb & 0xFFFFFC00u) < thrv) continue;
            int idx = (int)(pb & 1023u);
            const float4* er = (const float4*)(emb + (size_t)idx * DV);
            float Mf = 0.f;
#pragma unroll 8
            for (int i = 0; i < DV / 4; i++) {
                float4 xv = xr[i]; float4 ev = er[i];
                Mf = __fmaf_rn(xv.x, ev.x, Mf);
                Mf = __fmaf_rn(xv.y, ev.y, Mf);
                Mf = __fmaf_rn(xv.z, ev.z, Mf);
                Mf = __fmaf_rn(xv.w, ev.w, Mf);
            }
            float Bf = g_bsq[idx];
            float dq = __fsub_rn(__fadd_rn(Af, Bf), __fmul_rn(2.0f, Mf));
            if (dq < bestq || (dq == bestq && idx < besti)) { bestq = dq; besti = idx; }
        }
        ((int*)(smem + OFF_IDX))[t] = besti;
        bestd64 = (double)bestq;
    }

    /* ---- loss reduction ---- */
    {
        double v = (t < 128) ? bestd64 : 0.0;
#pragma unroll
        for (int o = 16; o; o >>= 1)
            v += __longlong_as_double(__shfl_down_sync(0xffffffffu, __double_as_longlong(v), o));
        if (l == 0) ((double*)(smem + OFF_RED))[w] = v;
    }
    __syncthreads();
    if (t == 0) {
        double s = 0.0;
#pragma unroll
        for (int i = 0; i < 8; i++) s += ((double*)(smem + OFF_RED))[i];
        atomicAdd(&g_loss_acc, s);
    }

    /* ---- coalesced gather write: out[row] = emb[idx[row]] ---- */
    const int* sidx = (const int*)(smem + OFF_IDX);
    const float4* e4 = (const float4*)emb;
    float4* o4 = (float4*)outq;
#pragma unroll 4
    for (int i = t; i < MTILE * (DV / 4); i += 256) {
        int r = i >> 6, cc = i & 63;
        o4[(size_t)(m0 + r) * (DV / 4) + cc] = e4[(size_t)sidx[r] * (DV / 4) + cc];
    }
}

/* ---------------- Kernel C: finalize loss ---------------- */
__global__ void vq_finalize(float* loss_out, double inv_n) {
    if (threadIdx.x == 0) *loss_out = (float)(2.0 * g_loss_acc * inv_n);
}

extern "C" void kernel_launch(void* const* d_in, const int* in_sizes, int n_in,
                              void* d_out, int out_size) {
    const float* x   = (const float*)d_in[0];
    const float* emb = (const float*)d_in[1];
    float* out = (float*)d_out;
    const int nx = in_sizes[0];          /* 64*32*32*256 = 16777216 */
    const int rows = nx / DV;            /* 65536 */

    cudaFuncSetAttribute(vq_main, cudaFuncAttributeMaxDynamicSharedMemorySize, SMEM_TOTAL);

    vq_prep<<<KEMB, 256>>>(emb);
    vq_main<<<rows / MTILE, 256, SMEM_TOTAL>>>(x, emb, out);
    vq_finalize<<<1, 32>>>(out + (out_size - 1), 1.0 / (double)nx);
}

// round 11
// speedup vs baseline: 1.4984x; 1.1264x over previous
#include <cuda_runtime.h>
#include <cuda_bf16.h>
#include <cstdint>

#define DV      256
#define KEMB    1024
#define MTILE   128
#define NTILE   128
#define NCHUNK  8
#define KSTEP   8            /* 256 / 32 per e4m3 MMA */

/* dynamic smem layout (bytes) */
#define OFF_A       0        /* 128 x 256B fp8 X tile (swizzled)         */
#define OFF_B       32768    /* 128 x 256B fp8 E chunk (swizzled)        */
#define OFF_SC      65536    /* 1024 x float2 {se, 16-0.5||e||^2} = 8KB  */
#define OFF_SX      73728    /* 128 floats: per-row x scale              */
#define OFF_CAND    74240    /* 128 rows x 32 packed cands = 16KB        */
#define OFF_IDX     90624    /* 128 ints winning index per row           */
#define OFF_RED     91136    /* 8 doubles loss partials                  */
#define SMEM_TOTAL  91200

#define FP8_MAX  240.0f      /* map row absmax to 240 (< 448 e4m3 max)   */

__device__ __align__(16) uint32_t g_emb_f8[KEMB * (DV / 4)];
__device__ __align__(16) float2 g_sb[KEMB];   /* {se, 16 - 0.5*||e||^2} */
__device__ float  g_bsq[KEMB];                /* ||e||^2 ref-order fp32 */
__device__ double g_loss_acc;

static __device__ __forceinline__ uint32_t smem_u32(const void* p) {
    uint32_t a;
    asm("{ .reg .u64 t; cvta.to.shared.u64 t, %1; cvt.u32.u64 %0, t; }" : "=r"(a) : "l"(p));
    return a;
}

/* XOR swizzle on 16B chunks within a 256B row */
static __device__ __forceinline__ uint32_t swz(int row, int chunk) {
    return (uint32_t)(row * 256) + (uint32_t)((chunk ^ (row & 7)) << 4);
}

static __device__ __forceinline__ void ldsm4(uint32_t* r, uint32_t addr) {
    asm volatile("ldmatrix.sync.aligned.m8n8.x4.shared.b16 {%0,%1,%2,%3}, [%4];"
                 : "=r"(r[0]), "=r"(r[1]), "=r"(r[2]), "=r"(r[3]) : "r"(addr));
}

/* e4m3 MMA: D[16,8] += A[16,32] * B[32,8], f32 accum.
   Byte-level fragment layout identical to s8 k32 -> same ldmatrix feed. */
static __device__ __forceinline__ void mmaf8(float* c, const uint32_t* a,
                                             uint32_t b0, uint32_t b1) {
    asm volatile(
        "mma.sync.aligned.m16n8k32.row.col.f32.e4m3.e4m3.f32 "
        "{%0,%1,%2,%3}, {%4,%5,%6,%7}, {%8,%9}, {%0,%1,%2,%3};"
        : "+f"(c[0]), "+f"(c[1]), "+f"(c[2]), "+f"(c[3])
        : "r"(a[0]), "r"(a[1]), "r"(a[2]), "r"(a[3]), "r"(b0), "r"(b1));
}

/* sorted top-4 insert on packed {score|idx} uints */
static __device__ __forceinline__ void ins4(uint32_t* L, uint32_t pb) {
    if (pb > L[3]) {
        if (pb > L[1]) {
            if (pb > L[0]) { L[3] = L[2]; L[2] = L[1]; L[1] = L[0]; L[0] = pb; }
            else           { L[3] = L[2]; L[2] = L[1]; L[1] = pb; }
        } else {
            if (pb > L[2]) { L[3] = L[2]; L[2] = pb; }
            else           { L[3] = pb; }
        }
    }
}

/* pack 4 floats (scaled) into 4 e4m3 bytes */
static __device__ __forceinline__ uint32_t pack4f8(float4 v, float inv) {
    uint16_t lo, hi;
    asm("cvt.rn.satfinite.e4m3x2.f32 %0, %1, %2;" : "=h"(lo) : "f"(v.y * inv), "f"(v.x * inv));
    asm("cvt.rn.satfinite.e4m3x2.f32 %0, %1, %2;" : "=h"(hi) : "f"(v.w * inv), "f"(v.z * inv));
    return (uint32_t)lo | ((uint32_t)hi << 16);
}

/* ---------------- Kernel A: codebook prep ----------------
   per-row e4m3 quantization + scale; ||e||^2 in the reference's exact
   order (strictly sequential fp32 adds of unfused products). */
__global__ void vq_prep(const float* __restrict__ emb) {
    int b = blockIdx.x, t = threadIdx.x;           /* 1024 blocks x 256 threads */
    float v = emb[(size_t)b * DV + t];
    float av = fabsf(v);
#pragma unroll
    for (int o = 16; o; o >>= 1) av = fmaxf(av, __shfl_xor_sync(0xffffffffu, av, o));
    __shared__ float sw[8];
    __shared__ float smax;
    if ((t & 31) == 0) sw[t >> 5] = av;
    __syncthreads();
    if (t == 0) {
        float m = sw[0];
#pragma unroll
        for (int i = 1; i < 8; i++) m = fmaxf(m, sw[i]);
        smax = m;
    }
    __syncthreads();
    float m = smax;
    float inv = FP8_MAX / m;
    float v1 = __shfl_down_sync(0xffffffffu, v, 1);
    uint16_t h;
    asm("cvt.rn.satfinite.e4m3x2.f32 %0, %1, %2;" : "=h"(h) : "f"(v1 * inv), "f"(v * inv));
    uint32_t h2 = __shfl_down_sync(0xffffffffu, (uint32_t)h, 2);
    if ((t & 3) == 0)
        g_emb_f8[b * 64 + (t >> 2)] = (uint32_t)h | (h2 << 16);
    if (t == 0) {
        const float4* er = (const float4*)(emb + (size_t)b * DV);
        float s = 0.f;
#pragma unroll 8
        for (int i = 0; i < DV / 4; i++) {
            float4 e = er[i];
            s = __fadd_rn(s, __fmul_rn(e.x, e.x));
            s = __fadd_rn(s, __fmul_rn(e.y, e.y));
            s = __fadd_rn(s, __fmul_rn(e.z, e.z));
            s = __fadd_rn(s, __fmul_rn(e.w, e.w));
        }
        g_bsq[b] = s;
        g_sb[b] = make_float2(m * (1.0f / FP8_MAX), 16.0f - 0.5f * s);
        if (b == 0) g_loss_acc = 0.0;
    }
}

/* ---------------- Kernel B: main ---------------- */
__global__ void __launch_bounds__(256, 2)
vq_main(const float* __restrict__ x, const float* __restrict__ emb, float* __restrict__ outq) {
    extern __shared__ char smem[];
    const uint32_t sb = smem_u32(smem);
    const int t = threadIdx.x;
    const int w = t >> 5;
    const int l = t & 31;
    const int m0 = blockIdx.x * MTILE;

    /* ---- stage per-code {se, 16-bias} table ---- */
    {
        const float4* src = (const float4*)g_sb;
        float4* dst = (float4*)(smem + OFF_SC);
        dst[t] = src[t];
        dst[t + 256] = src[t + 256];
    }

    /* ---- X: per-row absmax then e4m3 quantize into swizzled smem ---- */
    {
        int row = t >> 1, half = t & 1;
        const float4* xr = (const float4*)(x + (size_t)(m0 + row) * DV + half * 128);
        float mx = 0.f;
#pragma unroll 8
        for (int i = 0; i < 32; i++) {
            float4 v = xr[i];
            mx = fmaxf(mx, fmaxf(fmaxf(fabsf(v.x), fabsf(v.y)), fmaxf(fabsf(v.z), fabsf(v.w))));
        }
        mx = fmaxf(mx, __shfl_xor_sync(0xffffffffu, mx, 1));
        float inv = FP8_MAX / mx;
        if (half == 0) ((float*)(smem + OFF_SX))[row] = mx * (1.0f / FP8_MAX);
#pragma unroll
        for (int c = 0; c < 8; c++) {
            uint4 st;
            st.x = pack4f8(xr[4 * c + 0], inv);
            st.y = pack4f8(xr[4 * c + 1], inv);
            st.z = pack4f8(xr[4 * c + 2], inv);
            st.w = pack4f8(xr[4 * c + 3], inv);
            *reinterpret_cast<uint4*>(smem + OFF_A + swz(row, half * 8 + c)) = st;
        }
    }
    __syncthreads();

    /* warp tile: rows wr..wr+31, cols wc..wc+63 of the 128x128 chunk scores */
    const int wr = (w >> 1) * 32, wc = (w & 1) * 64;
    const uint32_t aoff = (uint32_t)(l >> 4);
    const uint32_t boff = (uint32_t)((l >> 3) & 1);
    uint32_t aAddr[2], aX[2], bAddr[4], bX[4];
#pragma unroll
    for (int i = 0; i < 2; i++) {
        int r = wr + i * 16 + (l & 7) + ((l >> 3) & 1) * 8;
        aAddr[i] = sb + OFF_A + (uint32_t)(r * 256);
        aX[i] = (uint32_t)(r & 7);
    }
#pragma unroll
    for (int nt = 0; nt < 4; nt++) {
        int r = wc + nt * 16 + (l & 7) + ((l >= 16) ? 8 : 0);
        bAddr[nt] = sb + OFF_B + (uint32_t)(r * 256);
        bX[nt] = (uint32_t)(r & 7);
    }
    const int erow = wr + (l >> 2);
    const int ecol = wc + (l & 3) * 2;

    /* per-thread rows: erow + (ri>>1)*16 + (ri&1)*8 */
    float sx[4];
#pragma unroll
    for (int ri = 0; ri < 4; ri++)
        sx[ri] = ((const float*)(smem + OFF_SX))[erow + (ri >> 1) * 16 + (ri & 1) * 8];

    uint32_t L[4][4];
#pragma unroll
    for (int ri = 0; ri < 4; ri++)
#pragma unroll
        for (int p = 0; p < 4; p++) L[ri][p] = 0u;

    const float4* scp = (const float4*)(smem + OFF_SC);

    for (int c = 0; c < NCHUNK; c++) {
        if (c) __syncthreads();    /* prior chunk's MMA reads of B done */
        /* ---- load E chunk c (e4m3) ---- */
        {
            int row = t >> 1, half = t & 1;
            const uint4* er = (const uint4*)(g_emb_f8 + (size_t)(c * NTILE + row) * 64) + half * 8;
#pragma unroll
            for (int k = 0; k < 8; k++)
                *reinterpret_cast<uint4*>(smem + OFF_B + swz(row, half * 8 + k)) = er[k];
        }
        __syncthreads();

        /* ---- GEMM: e4m3 dot products, f32 accum ---- */
        float acc[2][8][4];
#pragma unroll
        for (int i = 0; i < 2; i++)
#pragma unroll
            for (int j = 0; j < 8; j++)
#pragma unroll
                for (int q = 0; q < 4; q++) acc[i][j][q] = 0.f;

#pragma unroll
        for (int s = 0; s < KSTEP; s++) {
            uint32_t a[2][4], bfr[4][4];
#pragma unroll
            for (int i = 0; i < 2; i++)
                ldsm4(a[i], aAddr[i] + ((((uint32_t)(2 * s) + aoff) ^ aX[i]) << 4));
#pragma unroll
            for (int nt = 0; nt < 4; nt++)
                ldsm4(bfr[nt], bAddr[nt] + ((((uint32_t)(2 * s) + boff) ^ bX[nt]) << 4));
#pragma unroll
            for (int i = 0; i < 2; i++)
#pragma unroll
                for (int j = 0; j < 8; j++)
                    mmaf8(acc[i][j], a[i], bfr[j >> 1][(j & 1) * 2], bfr[j >> 1][(j & 1) * 2 + 1]);
        }

        /* ---- register-resident scan: s = sx*se*dot + (16 - 0.5||e||^2);
                pack {score, 10-bit code idx}, keep per-row top-4 ---- */
#pragma unroll
        for (int j = 0; j < 8; j++) {
            int colg = c * NTILE + ecol + j * 8;
            float4 sc2 = scp[colg >> 1];   /* {se0, c16_0, se1, c16_1} */
#pragma unroll
            for (int ri = 0; ri < 4; ri++) {
                int i = ri >> 1, qb = (ri & 1) * 2;
                float s0 = __fmaf_rn(sx[ri], sc2.x * acc[i][j][qb],     sc2.y);
                float s1 = __fmaf_rn(sx[ri], sc2.z * acc[i][j][qb + 1], sc2.w);
                ins4(L[ri], (__float_as_uint(s0) & 0xFFFFFC00u) | (uint32_t)colg);
                ins4(L[ri], (__float_as_uint(s1) & 0xFFFFFC00u) | (uint32_t)(colg + 1));
            }
        }
    }
    __syncthreads();

    /* ---- publish candidate lists: row r gets 32 packed entries ---- */
    {
        uint32_t* cand = (uint32_t*)(smem + OFF_CAND);
#pragma unroll
        for (int ri = 0; ri < 4; ri++) {
            int r = erow + (ri >> 1) * 16 + (ri & 1) * 8;
            *reinterpret_cast<uint4*>(cand + r * 32 + (w & 1) * 16 + (l & 3) * 4) =
                make_uint4(L[ri][0], L[ri][1], L[ri][2], L[ri][3]);
        }
    }
    __syncthreads();

    /* ---- refinement: replicate the reference's fp32 arithmetic ORDER
            (validated R8): A = seq unfused sum of x*x; M = seq FMA chain;
            d = fl(fl(A+B) - 2*M); argmin ties -> lowest index. ---- */
    double bestd64 = 0.0;
    if (t < 128) {
        const uint32_t* cl = (const uint32_t*)(smem + OFF_CAND) + t * 32;
        uint32_t cb[32];
#pragma unroll
        for (int k = 0; k < 8; k++)
            *reinterpret_cast<uint4*>(cb + k * 4) = reinterpret_cast<const uint4*>(cl)[k];
        uint32_t bestpb = 0;
#pragma unroll
        for (int k = 0; k < 32; k++) bestpb = max(bestpb, cb[k]);
        float thrv = __uint_as_float(bestpb & 0xFFFFFC00u) - 0.25f;  /* ~13-sigma fp8 noise */

        const float4* xr = (const float4*)(x + (size_t)(m0 + t) * DV);
        float Af = 0.f;
#pragma unroll 8
        for (int i = 0; i < DV / 4; i++) {
            float4 v = xr[i];
            Af = __fadd_rn(Af, __fmul_rn(v.x, v.x));
            Af = __fadd_rn(Af, __fmul_rn(v.y, v.y));
            Af = __fadd_rn(Af, __fmul_rn(v.z, v.z));
            Af = __fadd_rn(Af, __fmul_rn(v.w, v.w));
        }

        float bestq = 3.4e38f; int besti = 0x7fffffff;
#pragma unroll 1
        for (int k = 0; k < 32; k++) {
            uint32_t pb = cb[k];
            if (__uint_as_float(pb & 0xFFFFFC00u) < thrv) continue;
            int idx = (int)(pb & 1023u);
            const float4* er = (const float4*)(emb + (size_t)idx * DV);
            float Mf = 0.f;
#pragma unroll 8
            for (int i = 0; i < DV / 4; i++) {
                float4 xv = xr[i]; float4 ev = er[i];
                Mf = __fmaf_rn(xv.x, ev.x, Mf);
                Mf = __fmaf_rn(xv.y, ev.y, Mf);
                Mf = __fmaf_rn(xv.z, ev.z, Mf);
                Mf = __fmaf_rn(xv.w, ev.w, Mf);
            }
            float Bf = g_bsq[idx];
            float dq = __fsub_rn(__fadd_rn(Af, Bf), __fmul_rn(2.0f, Mf));
            if (dq < bestq || (dq == bestq && idx < besti)) { bestq = dq; besti = idx; }
        }
        ((int*)(smem + OFF_IDX))[t] = besti;
        bestd64 = (double)bestq;
    }

    /* ---- loss reduction ---- */
    {
        double v = (t < 128) ? bestd64 : 0.0;
#pragma unroll
        for (int o = 16; o; o >>= 1)
            v += __longlong_as_double(__shfl_down_sync(0xffffffffu, __double_as_longlong(v), o));
        if (l == 0) ((double*)(smem + OFF_RED))[w] = v;
    }
    __syncthreads();
    if (t == 0) {
        double s = 0.0;
#pragma unroll
        for (int i = 0; i < 8; i++) s += ((double*)(smem + OFF_RED))[i];
        atomicAdd(&g_loss_acc, s);
    }

    /* ---- coalesced gather write: out[row] = emb[idx[row]] ---- */
    const int* sidx = (const int*)(smem + OFF_IDX);
    const float4* e4 = (const float4*)emb;
    float4* o4 = (float4*)outq;
#pragma unroll 4
    for (int i = t; i < MTILE * (DV / 4); i += 256) {
        int r = i >> 6, cc = i & 63;
        o4[(size_t)(m0 + r) * (DV / 4) + cc] = e4[(size_t)sidx[r] * (DV / 4) + cc];
    }
}

/* ---------------- Kernel C: finalize loss ---------------- */
__global__ void vq_finalize(float* loss_out, double inv_n) {
    if (threadIdx.x == 0) *loss_out = (float)(2.0 * g_loss_acc * inv_n);
}

extern "C" void kernel_launch(void* const* d_in, const int* in_sizes, int n_in,
                              void* d_out, int out_size) {
    const float* x   = (const float*)d_in[0];
    const float* emb = (const float*)d_in[1];
    float* out = (float*)d_out;
    const int nx = in_sizes[0];          /* 64*32*32*256 = 16777216 */
    const int rows = nx / DV;            /* 65536 */

    cudaFuncSetAttribute(vq_main, cudaFuncAttributeMaxDynamicSharedMemorySize, SMEM_TOTAL);

    vq_prep<<<KEMB, 256>>>(emb);
    vq_main<<<rows / MTILE, 256, SMEM_TOTAL>>>(x, emb, out);
    vq_finalize<<<1, 32>>>(out + (out_size - 1), 1.0 / (double)nx);
}